// round 11
// baseline (speedup 1.0000x reference)
#include <cuda_runtime.h>
#include <cuda_bf16.h>
#include <cstdint>
#include <math.h>

#define N_TOK 8192
#define C_DIM 1024
#define E_NUM 8
#define DFF_DIM 4096
#define HROWS (2 * N_TOK + 128)

// ---------------- scratch (~270MB total — proven-passing level) ---------------
__device__ float g_h[HROWS * DFF_DIM];     // fp32 gelu(x@w1) rows, bucketed
__device__ int   g_counts[E_NUM];
__device__ int   g_offsets[E_NUM];
__device__ int   g_tok[E_NUM * N_TOK];
__device__ float g_wgt[E_NUM * N_TOK];

// ---------------- helpers -----------------------------------------------------
__device__ __forceinline__ void mma_bf16(float* d, const uint32_t* a, const uint32_t* b) {
    asm volatile(
        "mma.sync.aligned.m16n8k16.row.col.f32.bf16.bf16.f32 "
        "{%0,%1,%2,%3}, {%4,%5,%6,%7}, {%8,%9}, {%0,%1,%2,%3};"
        : "+f"(d[0]), "+f"(d[1]), "+f"(d[2]), "+f"(d[3])
        : "r"(a[0]), "r"(a[1]), "r"(a[2]), "r"(a[3]), "r"(b[0]), "r"(b[1]));
}

// truncation split of a pair: hi = top 16 bits (exact trunc), lo = exact residual
__device__ __forceinline__ void tsplit2(float vx, float vy, uint32_t& hi, uint32_t& lo) {
    uint32_t ax = __float_as_uint(vx), ay = __float_as_uint(vy);
    float lx = vx - __uint_as_float(ax & 0xFFFF0000u);
    float ly = vy - __uint_as_float(ay & 0xFFFF0000u);
    hi = __byte_perm(ax, ay, 0x7632);
    lo = __byte_perm(__float_as_uint(lx), __float_as_uint(ly), 0x7632);
}

__device__ __forceinline__ float gelu_exact(float v) {
    return 0.5f * v * (1.0f + erff(v * 0.70710678118654752f));
}

// ---------------- small kernels (verbatim) -------------------------------------
__global__ void zero_counts_kernel() {
    if (threadIdx.x < E_NUM) g_counts[threadIdx.x] = 0;
}
__global__ void zero_out_kernel(float* out, int n) {
    for (int i = blockIdx.x * blockDim.x + threadIdx.x; i < n; i += gridDim.x * blockDim.x)
        out[i] = 0.0f;
}
__global__ void offsets_kernel() {
    int run = 0;
    for (int e = 0; e < E_NUM; e++) { g_offsets[e] = run; run += g_counts[e]; }
}

__global__ void router_kernel(const float* __restrict__ x,
                              const float* __restrict__ rw,
                              const float* __restrict__ rb) {
    int t = blockIdx.x;
    int tid = threadIdx.x;
    __shared__ float red[128][E_NUM];
    float acc[E_NUM];
#pragma unroll
    for (int e = 0; e < E_NUM; e++) acc[e] = 0.0f;
    const float* xr = x + (size_t)t * C_DIM;
    for (int c = tid; c < C_DIM; c += 128) {
        float xv = xr[c];
        const float* w = &rw[c * E_NUM];
#pragma unroll
        for (int e = 0; e < E_NUM; e++) acc[e] += xv * w[e];
    }
#pragma unroll
    for (int e = 0; e < E_NUM; e++) red[tid][e] = acc[e];
    __syncthreads();
    for (int s = 64; s > 0; s >>= 1) {
        if (tid < s) {
#pragma unroll
            for (int e = 0; e < E_NUM; e++) red[tid][e] += red[tid + s][e];
        }
        __syncthreads();
    }
    if (tid == 0) {
        float lg[E_NUM], p[E_NUM];
        float mx = -1e30f;
#pragma unroll
        for (int e = 0; e < E_NUM; e++) { lg[e] = red[0][e] + rb[e]; mx = fmaxf(mx, lg[e]); }
        float sum = 0.0f;
#pragma unroll
        for (int e = 0; e < E_NUM; e++) { p[e] = expf(lg[e] - mx); sum += p[e]; }
        float inv = 1.0f / sum;
#pragma unroll
        for (int e = 0; e < E_NUM; e++) p[e] *= inv;
        int i1 = 0;
#pragma unroll
        for (int e = 1; e < E_NUM; e++) if (p[e] > p[i1]) i1 = e;
        int i2 = (i1 == 0) ? 1 : 0;
#pragma unroll
        for (int e = 0; e < E_NUM; e++) if (e != i1 && p[e] > p[i2]) i2 = e;
        int s1 = atomicAdd(&g_counts[i1], 1);
        g_tok[i1 * N_TOK + s1] = t;  g_wgt[i1 * N_TOK + s1] = p[i1];
        int s2 = atomicAdd(&g_counts[i2], 1);
        g_tok[i2 * N_TOK + s2] = t;  g_wgt[i2 * N_TOK + s2] = p[i2];
    }
}

// ---------------- HMMA GEMM with smem-staged packed fragments ------------------
// Round-10 structure; ONLY change: term-major MMA issue order (16 independent
// MMAs between reuses of the same accumulator — hides HMMA RAW latency).
template <int KTOT, int NDIM, bool G1>
__global__ void __launch_bounds__(256, 1)
gemm_hmma(const float* __restrict__ A_g, const float* __restrict__ B_g,
          const float* __restrict__ bias_g, float* __restrict__ out) {
    __shared__ __align__(16) uint32_t sAh[2 * 128 * 8];
    __shared__ __align__(16) uint32_t sAl[2 * 128 * 8];
    __shared__ __align__(16) uint32_t sBh[2 * 128 * 10];
    __shared__ __align__(16) uint32_t sBl[2 * 128 * 10];
    __shared__ int   srow_s[128];
    __shared__ int   stok_s[128];
    __shared__ float swgt_s[128];

    int e = blockIdx.z;
    int cnt = g_counts[e];
    int m0 = blockIdx.y * 128;
    if (m0 >= cnt) return;
    int n0 = blockIdx.x * 128;
    int off = g_offsets[e];

    int tid = threadIdx.x, lane = tid & 31, wid = tid >> 5;
    int wm = wid >> 2, wn = wid & 3;
    int l4 = lane >> 2, lc = lane & 3;

    if (tid < 128) {
        int m = m0 + tid;
        int sr = 0, tk = 0; float wg = 0.0f;
        if (m < cnt) {
            tk = g_tok[e * N_TOK + m];
            wg = g_wgt[e * N_TOK + m];
            sr = G1 ? tk : (off + m);
        }
        srow_s[tid] = sr; stok_s[tid] = tk; swgt_s[tid] = wg;
    }
    __syncthreads();

    const float* Abase = G1 ? A_g : g_h;
    const float* Bp = B_g + (size_t)e * KTOT * NDIM + n0;
    const float* bias = bias_g + (size_t)e * NDIM + n0;

    int prA = tid & 15;
    int sA = prA >> 3, wA = prA & 7;
    int posA = (wA & 3) * 2 + (wA >> 2);
    const float* aptr[8];
    int aws[8];
#pragma unroll
    for (int i = 0; i < 8; i++) {
        int r = (tid >> 4) + 16 * i;
        aptr[i] = Abase + (size_t)srow_s[r] * KTOT + 2 * prA;
        aws[i] = (sA * 128 + r) * 8 + posA;
    }
    int nB = tid & 127;
    const float* bptr[8];
    int bws[8];
#pragma unroll
    for (int i = 0; i < 8; i++) {
        int pk = (tid >> 7) + 2 * i;
        int sB = pk >> 3, wB = pk & 7;
        int posB = (wB & 3) * 2 + (wB >> 2);
        bptr[i] = Bp + (size_t)(2 * pk) * NDIM + nB;
        bws[i] = (sB * 128 + nB) * 10 + posB;
    }

    float acc[4][4][4];
#pragma unroll
    for (int a = 0; a < 4; a++)
#pragma unroll
        for (int b = 0; b < 4; b++)
#pragma unroll
            for (int c = 0; c < 4; c++) acc[a][b][c] = 0.0f;

    const int NS = KTOT / 32;
    float2 pa[8];
    float pbx[8], pby[8];
#pragma unroll
    for (int i = 0; i < 8; i++) pa[i] = *(const float2*)(aptr[i]);
#pragma unroll
    for (int i = 0; i < 8; i++) { pbx[i] = bptr[i][0]; pby[i] = bptr[i][NDIM]; }

    for (int s = 0; s < NS; s++) {
        __syncthreads();
#pragma unroll
        for (int i = 0; i < 8; i++) {
            uint32_t hi, lo;
            tsplit2(pa[i].x, pa[i].y, hi, lo);
            sAh[aws[i]] = hi;
            sAl[aws[i]] = lo;
        }
#pragma unroll
        for (int i = 0; i < 8; i++) {
            uint32_t hi, lo;
            tsplit2(pbx[i], pby[i], hi, lo);
            sBh[bws[i]] = hi;
            sBl[bws[i]] = lo;
        }
        __syncthreads();
        if (s + 1 < NS) {
            size_t ka = (size_t)(s + 1) * 32;
#pragma unroll
            for (int i = 0; i < 8; i++) pa[i] = *(const float2*)(aptr[i] + ka);
            size_t kb = ka * NDIM;
#pragma unroll
            for (int i = 0; i < 8; i++) {
                pbx[i] = *(bptr[i] + kb);
                pby[i] = *(bptr[i] + kb + NDIM);
            }
        }

#pragma unroll
        for (int ks = 0; ks < 2; ks++) {
            // load ALL fragments for this k16 slice first
            uint32_t bhf[4][2], blf[4][2];
#pragma unroll
            for (int nt = 0; nt < 4; nt++) {
                int n = wn * 32 + nt * 8 + l4;
                int wbi = (ks * 128 + n) * 10 + 2 * lc;
                uint2 h = *(const uint2*)&sBh[wbi];
                uint2 l = *(const uint2*)&sBl[wbi];
                bhf[nt][0] = h.x; bhf[nt][1] = h.y;
                blf[nt][0] = l.x; blf[nt][1] = l.y;
            }
            uint32_t ahf[4][4], alf[4][4];
#pragma unroll
            for (int mt = 0; mt < 4; mt++) {
                int r = wm * 64 + mt * 16 + l4;
                int wa0 = (ks * 128 + r) * 8 + 2 * lc;
                int wa1 = (ks * 128 + r + 8) * 8 + 2 * lc;
                uint2 h0 = *(const uint2*)&sAh[wa0];
                uint2 h1 = *(const uint2*)&sAh[wa1];
                uint2 l0 = *(const uint2*)&sAl[wa0];
                uint2 l1 = *(const uint2*)&sAl[wa1];
                ahf[mt][0] = h0.x; ahf[mt][1] = h1.x; ahf[mt][2] = h0.y; ahf[mt][3] = h1.y;
                alf[mt][0] = l0.x; alf[mt][1] = l1.x; alf[mt][2] = l0.y; alf[mt][3] = l1.y;
            }
            // term-major issue: same-acc reuse spaced 16 independent MMAs apart
#pragma unroll
            for (int mt = 0; mt < 4; mt++)
#pragma unroll
                for (int nt = 0; nt < 4; nt++)
                    mma_bf16(acc[mt][nt], ahf[mt], bhf[nt]);
#pragma unroll
            for (int mt = 0; mt < 4; mt++)
#pragma unroll
                for (int nt = 0; nt < 4; nt++)
                    mma_bf16(acc[mt][nt], ahf[mt], blf[nt]);
#pragma unroll
            for (int mt = 0; mt < 4; mt++)
#pragma unroll
                for (int nt = 0; nt < 4; nt++)
                    mma_bf16(acc[mt][nt], alf[mt], bhf[nt]);
        }
    }

    // ---- epilogue (verbatim) ----
#pragma unroll
    for (int mt = 0; mt < 4; mt++) {
#pragma unroll
        for (int half = 0; half < 2; half++) {
            int mrow = wm * 64 + mt * 16 + l4 + half * 8;
            if (m0 + mrow >= cnt) continue;
            if (G1) {
                float* hrow = g_h + (size_t)(off + m0 + mrow) * DFF_DIM + n0;
#pragma unroll
                for (int nt = 0; nt < 4; nt++) {
                    int c = wn * 32 + nt * 8 + lc * 2;
                    float v0 = gelu_exact(acc[mt][nt][half * 2 + 0] + bias[c]);
                    float v1 = gelu_exact(acc[mt][nt][half * 2 + 1] + bias[c + 1]);
                    *(float2*)(hrow + c) = make_float2(v0, v1);
                }
            } else {
                int tok = stok_s[mrow];
                float wgt = swgt_s[mrow];
                float* orow = out + (size_t)tok * C_DIM + n0;
#pragma unroll
                for (int nt = 0; nt < 4; nt++) {
                    int c = wn * 32 + nt * 8 + lc * 2;
                    atomicAdd(orow + c,     wgt * (acc[mt][nt][half * 2 + 0] + bias[c]));
                    atomicAdd(orow + c + 1, wgt * (acc[mt][nt][half * 2 + 1] + bias[c + 1]));
                }
            }
        }
    }
}

// ---------------- launch ------------------------------------------------------
extern "C" void kernel_launch(void* const* d_in, const int* in_sizes, int n_in,
                              void* d_out, int out_size) {
    const float* x  = (const float*)d_in[0];
    const float* rw = (const float*)d_in[1];
    const float* rb = (const float*)d_in[2];
    const float* w1 = (const float*)d_in[3];
    const float* b1 = (const float*)d_in[4];
    const float* w2 = (const float*)d_in[5];
    const float* b2 = (const float*)d_in[6];
    float* out = (float*)d_out;

    zero_counts_kernel<<<1, 32>>>();
    router_kernel<<<N_TOK, 128>>>(x, rw, rb);
    offsets_kernel<<<1, 1>>>();
    zero_out_kernel<<<512, 256>>>(out, N_TOK * C_DIM);

    {
        dim3 g(DFF_DIM / 128, N_TOK / 128, E_NUM);
        gemm_hmma<C_DIM, DFF_DIM, true><<<g, 256>>>(x, w1, b1, nullptr);
    }
    {
        dim3 g(C_DIM / 128, N_TOK / 128, E_NUM);
        gemm_hmma<DFF_DIM, C_DIM, false><<<g, 256>>>(nullptr, w2, b2, out);
    }
}